// round 10
// baseline (speedup 1.0000x reference)
#include <cuda_runtime.h>

#define DD   512
#define KK   16
#define TPB  128           // 4 warps; warp owns 64 rows, all 16 k, 2 rows/thread
#define RPB  256           // rows per block
#define CH   16            // dims per chunk = 64B per row
#define NCH  (DD/CH)       // 32 chunks
#define NSTG 2

// ---- dynamic smem layout (bytes) ----
#define SM_CB     0                      // codebook: 32768
#define SM_ZSTG   32768                  // staging: 2 stages * 4 warps * 4096 = 32768
#define SM_SDIST  65536                  // 128 * 4
#define SM_SIDX   66048                  // 256 * 4
#define SM_C2S    67072                  // 16 * 4
#define SM_TICKET 67136                  // 4
#define SM_TOTAL  67200

// ---- device scratch (no allocations allowed) ----
__device__ float g_bsum[4096];
__device__ unsigned int g_done = 0;

// ---- packed f32x2 helpers (Blackwell FFMA2) ----
__device__ __forceinline__ void upk2(unsigned long long v, float& lo, float& hi) {
    asm("mov.b64 {%0,%1}, %2;" : "=f"(lo), "=f"(hi) : "l"(v));
}
__device__ __forceinline__ unsigned long long ffma2(unsigned long long a,
                                                    unsigned long long b,
                                                    unsigned long long c) {
    unsigned long long d;
    asm("fma.rn.f32x2 %0, %1, %2, %3;" : "=l"(d) : "l"(a), "l"(b), "l"(c));
    return d;
}
__device__ __forceinline__ void cpasync16(unsigned dst, const void* src) {
    asm volatile("cp.async.cg.shared.global [%0], [%1], 16;" :: "r"(dst), "l"(src) : "memory");
}
#define CP_COMMIT() asm volatile("cp.async.commit_group;" ::: "memory")
#define CP_WAIT(n)  asm volatile("cp.async.wait_group %0;" :: "n"(n) : "memory")

__global__ void __launch_bounds__(TPB, 3) vq_fused(
    const float* __restrict__ z, const float* __restrict__ cb,
    float* __restrict__ zq, float* __restrict__ idxp, float* __restrict__ lossp,
    int nrows, int nblocks, float scale)
{
    extern __shared__ char smem[];
    float*        sc     = (float*)(smem + SM_CB);
    float*        sdist  = (float*)(smem + SM_SDIST);
    int*          sidx   = (int*)(smem + SM_SIDX);
    float*        c2s    = (float*)(smem + SM_C2S);
    unsigned int* ticket = (unsigned int*)(smem + SM_TICKET);

    const int t = threadIdx.x;
    const int w = t >> 5, lane = t & 31;
    const int rowbase = blockIdx.x * RPB;
    const int lastrow = nrows - 1;

    const unsigned smem_sa = (unsigned)__cvta_generic_to_shared(smem);
    // staging for (stage s, warp w): SM_ZSTG + (s*4+w)*4096; inside: piece*1024 + row*16
    const unsigned stg_w = smem_sa + SM_ZSTG + (unsigned)(w * 4096);

    // cp.async roles: instr i stages rows i*8 + (lane>>2), piece = lane&3
    const int srow = lane >> 2;                  // 0..7
    const int sp   = lane & 3;                   // 0..3

    // issue chunk c into stage s: 8 cp.async x 16B per lane; 64B contiguous per row
    #define ISSUE(c, s) do {                                                        \
        _Pragma("unroll")                                                           \
        for (int i = 0; i < 8; i++) {                                               \
            int rr = i * 8 + srow;                                                  \
            int gr = rowbase + w * 64 + rr; if (gr > lastrow) gr = lastrow;         \
            const char* src = (const char*)z + (size_t)gr * (DD * 4)                \
                              + (size_t)(c) * (CH * 4) + sp * 16;                   \
            unsigned dst = stg_w + (unsigned)((s) * 16384)                          \
                           + (unsigned)(sp * 1024 + rr * 16);                       \
            cpasync16(dst, src);                                                    \
        }                                                                           \
        CP_COMMIT();                                                                \
    } while (0)

    // ---- prologue: stage chunk 0 ----
    ISSUE(0, 0);

    // ---- stage codebook (coalesced float4) ----
    for (int i = t; i < KK * DD / 4; i += TPB)
        ((float4*)sc)[i] = ((const float4*)cb)[i];
    __syncthreads();

    // ---- codebook squared norms (identical per-k arithmetic as before) ----
    #pragma unroll
    for (int kk = 0; kk < 4; kk++) {
        int k = w * 4 + kk;
        float s = 0.f;
        for (int j = lane; j < DD; j += 32) {
            float v = sc[k * DD + j];
            s = fmaf(v, v, s);
        }
        #pragma unroll
        for (int o = 16; o; o >>= 1) s += __shfl_xor_sync(0xffffffffu, s, o);
        if (lane == 0) c2s[k] = s;
    }
    __syncthreads();                     // c2s + sc visible; no block syncs until epilogue

    // ---- accumulators: one chain per k per row, bit-identical dim order to R9 ----
    unsigned long long acc0[KK], acc1[KK];
    #pragma unroll
    for (int k = 0; k < KK; k++) { acc0[k] = 0ull; acc1[k] = 0ull; }
    unsigned long long z2r0 = 0ull, z2r1 = 0ull;

    const char* stg_rd = (const char*)smem + SM_ZSTG + w * 4096;

    for (int c = 0; c < NCH; c++) {
        if (c + 1 < NCH) {
            ISSUE(c + 1, (c + 1) & 1);   // overlaps chunk c wait + compute
            CP_WAIT(1);                  // chunk c complete, c+1 in flight
        } else {
            CP_WAIT(0);
        }
        __syncwarp();                    // cross-lane staging visibility (warp-local)

        const char* rb = stg_rd + (c & 1) * 16384;
        const float* cbb = sc + c * CH;

        #pragma unroll
        for (int p = 0; p < 4; p++) {    // 4 pieces x 4 dims, ascending
            ulonglong2 zv0 = *(const ulonglong2*)(rb + p * 1024 + lane * 16);
            ulonglong2 zv1 = *(const ulonglong2*)(rb + p * 1024 + (lane + 32) * 16);
            z2r0 = ffma2(zv0.x, zv0.x, z2r0);  z2r0 = ffma2(zv0.y, zv0.y, z2r0);
            z2r1 = ffma2(zv1.x, zv1.x, z2r1);  z2r1 = ffma2(zv1.y, zv1.y, z2r1);
            #pragma unroll
            for (int k = 0; k < KK; k++) {
                // broadcast LDS.128 (same address across lanes), feeds BOTH rows
                ulonglong2 cv = *(const ulonglong2*)(cbb + k * DD + p * 4);
                acc0[k] = ffma2(zv0.x, cv.x, acc0[k]);
                acc0[k] = ffma2(zv0.y, cv.y, acc0[k]);
                acc1[k] = ffma2(zv1.x, cv.x, acc1[k]);
                acc1[k] = ffma2(zv1.y, cv.y, acc1[k]);
            }
        }
        __syncwarp();                    // all lanes done reading before next overwrite
    }

    // ---- argmin with reference-matching quantization (seq k=0..15, strict <) ----
    const int row0 = w * 64 + lane;            // block-local
    const int row1 = row0 + 32;
    float rloss = 0.f;
    {
        float lo, hi;
        upk2(z2r0, lo, hi);
        float z2s = lo + hi;
        float best = 3.4e38f; int bi = 0;
        #pragma unroll
        for (int k = 0; k < KK; k++) {
            upk2(acc0[k], lo, hi);
            float dot = lo + hi;
            float dist = (z2s - 2.0f * dot) + c2s[k];
            if (dist < best) { best = dist; bi = k; }
        }
        const int r = rowbase + row0;
        const bool active = r < nrows;
        if (active) rloss += best;
        sidx[row0] = bi;
        if (active && idxp) idxp[r] = (float)bi;
    }
    {
        float lo, hi;
        upk2(z2r1, lo, hi);
        float z2s = lo + hi;
        float best = 3.4e38f; int bi = 0;
        #pragma unroll
        for (int k = 0; k < KK; k++) {
            upk2(acc1[k], lo, hi);
            float dot = lo + hi;
            float dist = (z2s - 2.0f * dot) + c2s[k];
            if (dist < best) { best = dist; bi = k; }
        }
        const int r = rowbase + row1;
        const bool active = r < nrows;
        if (active) rloss += best;
        sidx[row1] = bi;
        if (active && idxp) idxp[r] = (float)bi;
    }
    sdist[t] = rloss;
    __syncthreads();

    // ---- cooperative coalesced z_q write: one full row per iteration ----
    float4* zqg = (float4*)zq;
    const int rmax = min(RPB, nrows - rowbase);
    for (int rr = 0; rr < rmax; rr++) {
        int b = sidx[rr];                                   // broadcast
        float4 cv = *(const float4*)(sc + b * DD + t * 4);  // lane-consecutive LDS.128
        zqg[(size_t)(rowbase + rr) * (DD / 4) + t] = cv;    // coalesced STG.128
    }

    // ---- deterministic block loss partial (tree over 128) ----
    #pragma unroll
    for (int s2 = 64; s2 > 0; s2 >>= 1) {
        if (t < s2) sdist[t] += sdist[t + s2];
        __syncthreads();
    }
    if (t == 0) g_bsum[blockIdx.x] = sdist[0];

    // ---- last-block finalize (deterministic order; counter reset for graph replay) ----
    if (t == 0) {
        __threadfence();
        ticket[0] = atomicAdd(&g_done, 1u);
    }
    __syncthreads();
    if (ticket[0] == (unsigned)(nblocks - 1)) {
        float s = 0.f;
        for (int i = t; i < nblocks; i += TPB) s += __ldcg(&g_bsum[i]);
        sdist[t] = s;
        __syncthreads();
        #pragma unroll
        for (int s2 = 64; s2 > 0; s2 >>= 1) {
            if (t < s2) sdist[t] += sdist[t + s2];
            __syncthreads();
        }
        if (t == 0) {
            if (lossp) lossp[0] = sdist[0] * scale;
            g_done = 0;
        }
    }
    #undef ISSUE
}

extern "C" void kernel_launch(void* const* d_in, const int* in_sizes, int n_in,
                              void* d_out, int out_size) {
    const float* z  = (const float*)d_in[0];
    const float* cb = (const float*)d_in[1];
    int zn = in_sizes[0];          // N * D
    int N  = zn / DD;

    float* zq = (float*)d_out;
    int has_idx  = (out_size >= zn + N) ? 1 : 0;
    float* idxp  = has_idx ? ((float*)d_out + zn) : nullptr;
    float* lossp = (out_size >= zn + N + 1) ? ((float*)d_out + zn + N) : nullptr;

    int nb = (N + RPB - 1) / RPB;
    float scale = 1.25f / ((float)N * (float)DD);

    cudaFuncSetAttribute(vq_fused, cudaFuncAttributeMaxDynamicSharedMemorySize, SM_TOTAL);
    vq_fused<<<nb, TPB, SM_TOTAL>>>(z, cb, zq, idxp, lossp, N, nb, scale);
}